// round 13
// baseline (speedup 1.0000x reference)
#include <cuda_runtime.h>
#include <cuda_fp16.h>
#include <cstdint>

#define IN_FEATS 128
#define HIDDEN   256
#define NMAX     100000

// fp16 per-node projections: u = Hs@W1a + b1, v = Hd@W1b
// 32B-aligned: edge pass gathers with v4.b64 (32B) loads.
__device__ __align__(32) unsigned short g_u[(size_t)NMAX * HIDDEN];
__device__ __align__(32) unsigned short g_v[(size_t)NMAX * HIDDEN];

// W1 fp16 swizzled B images: [isv(2)][n(256)][16 chunks of 16B]
__device__ uint4 g_Wf[2 * 256 * 16];

// ---------------------------------------------------------------------------
// helpers
// ---------------------------------------------------------------------------
__device__ __forceinline__ uint32_t smem_u32(const void* p) {
    uint32_t a;
    asm("{ .reg .u64 t; cvta.to.shared.u64 t, %1; cvt.u32.u64 %0, t; }"
        : "=r"(a) : "l"(p));
    return a;
}
__device__ __forceinline__ void cp_async16(uint32_t dst, const void* src) {
    asm volatile("cp.async.cg.shared.global [%0], [%1], 16;"
                 :: "r"(dst), "l"(src));
}
__device__ __forceinline__ void cp_async16z(uint32_t dst, const void* src,
                                            int srcsz) {
    asm volatile("cp.async.cg.shared.global [%0], [%1], 16, %2;"
                 :: "r"(dst), "l"(src), "r"(srcsz));
}
__device__ __forceinline__ void cp_async_commit() {
    asm volatile("cp.async.commit_group;");
}
__device__ __forceinline__ void cp_async_wait_all() {
    asm volatile("cp.async.wait_group 0;" ::: "memory");
}
__device__ __forceinline__ void ldsm4(uint32_t* r, uint32_t a) {
    asm volatile("ldmatrix.sync.aligned.m8n8.x4.shared.b16 {%0,%1,%2,%3}, [%4];"
                 : "=r"(r[0]), "=r"(r[1]), "=r"(r[2]), "=r"(r[3]) : "r"(a));
}
// m16n8k16 fp16 mma, fp32 accum
__device__ __forceinline__ void mma_f16(float* d, const uint32_t* a,
                                        const uint32_t* b) {
    asm volatile(
        "mma.sync.aligned.m16n8k16.row.col.f32.f16.f16.f32 "
        "{%0,%1,%2,%3}, {%4,%5,%6,%7}, {%8,%9}, {%0,%1,%2,%3};"
        : "+f"(d[0]), "+f"(d[1]), "+f"(d[2]), "+f"(d[3])
        : "r"(a[0]), "r"(a[1]), "r"(a[2]), "r"(a[3]), "r"(b[0]), "r"(b[1]));
}
__device__ __forceinline__ uint32_t pack_h2(float a, float b) {
    __half2 p = __floats2half2_rn(a, b);
    return *reinterpret_cast<uint32_t*>(&p);
}
// row-local XOR swizzle: rows 256B (128 fp16), chunk(16B) ^= (row & 7)
__device__ __forceinline__ uint32_t swz(uint32_t row, uint32_t kbyte) {
    return row * 256u + ((((kbyte >> 4) ^ (row & 7u)) << 4) | (kbyte & 15u));
}
// 32B gather with L2 evict_last (v4.b64 — the only legal evict form on sm_103)
__device__ __forceinline__ ulonglong4 ldg_el32(const void* p) {
    ulonglong4 r;
    asm volatile("ld.global.L2::evict_last.v4.b64 {%0,%1,%2,%3}, [%4];"
                 : "=l"(r.x), "=l"(r.y), "=l"(r.z), "=l"(r.w) : "l"(p));
    return r;
}

// ---------------------------------------------------------------------------
// prep_W: W1 -> fp16 swizzled B images (one-time, 128KB, L2-resident).
// ---------------------------------------------------------------------------
__global__ __launch_bounds__(256)
void prep_W(const float* __restrict__ W1)
{
    const int idx = blockIdx.x * 256 + threadIdx.x;
    if (idx >= 2 * 256 * 16) return;
    const int isv = idx >> 12;
    const int n   = (idx >> 4) & 255;
    const int c   = idx & 15;

    uint32_t p[4];
    #pragma unroll
    for (int j = 0; j < 4; j++) {
        const float w0 = W1[(size_t)(isv * 128 + c * 8 + 2 * j) * HIDDEN + n];
        const float w1 = W1[(size_t)(isv * 128 + c * 8 + 2 * j + 1) * HIDDEN + n];
        p[j] = pack_h2(w0, w1);
    }
    const int dst = (isv * 256 + n) * 16 + (c ^ (n & 7));
    g_Wf[dst] = make_uint4(p[0], p[1], p[2], p[3]);
}

// SMEM layout (dynamic), 32-row M tiles -> 2 CTAs/SM:
static constexpr int SM_B  = 0;           // 256 rows x 256B = 64KB
static constexpr int SM_A  = 65536;       // 32 rows x 256B = 8KB
static constexpr int SM_AF = 73728;       // fp32 staging 32 x 528B = 16896
static constexpr int AF_STRIDE = 528;
static constexpr int SM_TOTAL = 90624;

// issue cp.async for fp32 A tile (32 rows x 128 f32), ZFILL beyond M
__device__ __forceinline__ void load_A_async(const float* __restrict__ A,
                                             int M, int bm, uint32_t smb,
                                             int tid)
{
    #pragma unroll
    for (int i = 0; i < 4; i++) {
        const int o   = tid + i * 256;
        const int row = o >> 5;
        const int c   = o & 31;
        const float* src = A + (size_t)(bm + row) * IN_FEATS + c * 4;
        const uint32_t dst = smb + SM_AF + row * AF_STRIDE + c * 16;
        cp_async16z(dst, src, (bm + row < M) ? 16 : 0);
    }
    cp_async_commit();
}

// ---------------------------------------------------------------------------
// Persistent node GEMM (fp16): 2 CTAs/SM, 32-row M tiles — r11-verified.
// ---------------------------------------------------------------------------
__global__ __launch_bounds__(256, 2)
void node_gemm_persistent(const float* __restrict__ Hs,
                          const float* __restrict__ Hd,
                          const float* __restrict__ b1,
                          int M, int nTiles)
{
    extern __shared__ char smem[];
    __shared__ float sB1[HIDDEN];
    const uint32_t smb = smem_u32(smem);

    const int tid  = threadIdx.x;
    const int wid  = tid >> 5;
    const int lane = tid & 31;

    const bool is_u = (blockIdx.x & 1) == 0;
    const int  cta  = blockIdx.x >> 1;
    const int  nCta = gridDim.x >> 1;
    const float* __restrict__ A = is_u ? Hs : Hd;
    unsigned short* __restrict__ C = is_u ? g_u : g_v;

    {
        const uint4* srcB = g_Wf + (is_u ? 0 : 4096);
        #pragma unroll
        for (int i = 0; i < 16; i++) {
            const int o = tid + i * 256;
            cp_async16(smb + SM_B + o * 16, srcB + o);
        }
        cp_async_commit();
    }
    sB1[tid] = b1[tid];
    if (cta < nTiles) load_A_async(A, M, cta * 32, smb, tid);
    cp_async_wait_all();
    __syncthreads();

    const int nbase = wid * 32;

    const uint32_t rowA  = (uint32_t)(lane & 15);
    const uint32_t xorA  = rowA & 7u;
    const uint32_t chA0  = (uint32_t)(lane >> 4);
    const uint32_t baseA = rowA * 256u;

    const uint32_t rowB  = (uint32_t)(nbase + (lane & 7) + ((lane >> 4) << 3));
    const uint32_t xorB  = rowB & 7u;
    const uint32_t chB0  = (uint32_t)((lane >> 3) & 1);
    const uint32_t baseB = rowB * 256u;

    const int cvRow = tid >> 3;
    const int cvKq  = (tid & 7) * 16;
    const char* cvStage = smem + SM_AF + cvRow * AF_STRIDE;

    for (int t = cta; t < nTiles; t += nCta) {
        const int bm = t * 32;

        #pragma unroll
        for (int j = 0; j < 4; j++) {
            const int k = cvKq + j * 4;
            const float4 x = *reinterpret_cast<const float4*>(cvStage + k * 4);
            uint2 hv;
            hv.x = pack_h2(x.x, x.y);
            hv.y = pack_h2(x.z, x.w);
            const uint32_t o = swz((uint32_t)cvRow, (uint32_t)(k * 2));
            *reinterpret_cast<uint2*>(smem + SM_A + o) = hv;
        }
        __syncthreads();

        const int tn = t + nCta;
        if (tn < nTiles) load_A_async(A, M, tn * 32, smb, tid);

        float acc[2][4][4];
        #pragma unroll
        for (int mt = 0; mt < 2; mt++)
            #pragma unroll
            for (int nt = 0; nt < 4; nt++)
                #pragma unroll
                for (int q = 0; q < 4; q++) acc[mt][nt][q] = 0.f;

        #pragma unroll
        for (int ks = 0; ks < 8; ks++) {
            const uint32_t aAddr0 =
                smb + SM_A + baseA + (((chA0 + 2u * ks) ^ xorA) << 4);
            const uint32_t bAddr0 =
                smb + SM_B + baseB + (((chB0 + 2u * ks) ^ xorB) << 4);
            uint32_t af[2][4], bf[2][4];
            #pragma unroll
            for (int mt = 0; mt < 2; mt++)
                ldsm4(af[mt], aAddr0 + mt * 16 * 256);
            #pragma unroll
            for (int bt = 0; bt < 2; bt++)
                ldsm4(bf[bt], bAddr0 + bt * 16 * 256);
            #pragma unroll
            for (int mt = 0; mt < 2; mt++)
                #pragma unroll
                for (int bt = 0; bt < 2; bt++) {
                    mma_f16(acc[mt][2 * bt],     af[mt], &bf[bt][0]);
                    mma_f16(acc[mt][2 * bt + 1], af[mt], &bf[bt][2]);
                }
        }

        #pragma unroll
        for (int mt = 0; mt < 2; mt++) {
            const int m0 = mt * 16 + (lane >> 2);
            #pragma unroll
            for (int half = 0; half < 2; half++) {
                const int grow = bm + m0 + half * 8;
                if (grow >= M) continue;
                unsigned short* orow = C + (size_t)grow * HIDDEN;
                #pragma unroll
                for (int nt = 0; nt < 4; nt++) {
                    const int n = nbase + nt * 8 + (lane & 3) * 2;
                    float f0 = acc[mt][nt][2 * half];
                    float f1 = acc[mt][nt][2 * half + 1];
                    if (is_u) { f0 += sB1[n]; f1 += sB1[n + 1]; }
                    *reinterpret_cast<uint32_t*>(orow + n) = pack_h2(f0, f1);
                }
            }
        }

        cp_async_wait_all();
        __syncthreads();
    }
}

// ---------------------------------------------------------------------------
// Edge pass: half-warp per edge, 32B evict_last gathers.
// Lane c (0..15) covers hidden dims [c*16, c*16+16) — 16 lanes x 16 = 256.
// 2 edges per warp (one per half). W2 exact fp32 in registers.
// ---------------------------------------------------------------------------
__global__ __launch_bounds__(256)
void edge_score_kernel(const int* __restrict__ src,
                       const int* __restrict__ dst,
                       const float* __restrict__ W2,
                       const float* __restrict__ b2,
                       float* __restrict__ out,
                       int E)
{
    __shared__ float sW2[HIDDEN];
    const int tid = threadIdx.x;
    sW2[tid] = W2[tid];
    __syncthreads();

    const int lane = tid & 31;
    const int half = lane >> 4;
    const int c    = lane & 15;
    const int warp = tid >> 5;

    float w[16];
    #pragma unroll
    for (int j = 0; j < 4; j++) {
        const float4 t = *reinterpret_cast<const float4*>(&sW2[c * 16 + j * 4]);
        w[4 * j + 0] = t.x; w[4 * j + 1] = t.y;
        w[4 * j + 2] = t.z; w[4 * j + 3] = t.w;
    }
    const float bias = b2[0];

    const int e0 = (blockIdx.x * 8 + warp) * 2;
    if (e0 >= E) return;
    const int eA = min(e0 + half, E - 1);

    const int s = src[eA];
    const int d = dst[eA];

    const ulonglong4 ur = ldg_el32(g_u + (size_t)s * HIDDEN + c * 16);
    const ulonglong4 vr = ldg_el32(g_v + (size_t)d * HIDDEN + c * 16);
    const __half2* uh = reinterpret_cast<const __half2*>(&ur);
    const __half2* vh = reinterpret_cast<const __half2*>(&vr);

    float acc = 0.f;
    #pragma unroll
    for (int i = 0; i < 8; i++) {
        const float2 a = __half22float2(uh[i]);
        const float2 b = __half22float2(vh[i]);
        acc = fmaf(fmaxf(a.x + b.x, 0.f), w[2 * i], acc);
        acc = fmaf(fmaxf(a.y + b.y, 0.f), w[2 * i + 1], acc);
    }
    // reduce within the 16-lane half
    #pragma unroll
    for (int o = 8; o > 0; o >>= 1)
        acc += __shfl_xor_sync(0xFFFFFFFFu, acc, o);

    if (c == 0 && (e0 + half) < E)
        out[e0 + half] = acc + bias;
}

// ---------------------------------------------------------------------------
extern "C" void kernel_launch(void* const* d_in, const int* in_sizes, int n_in,
                              void* d_out, int out_size)
{
    const float* Hs = (const float*)d_in[0];
    const float* Hd = (const float*)d_in[1];
    const int*   src = (const int*)d_in[2];
    const int*   dst = (const int*)d_in[3];
    const float* W1 = (const float*)d_in[4];
    const float* b1 = (const float*)d_in[5];
    const float* W2 = (const float*)d_in[6];
    const float* b2 = (const float*)d_in[7];
    float* out = (float*)d_out;

    const int M = in_sizes[0] / IN_FEATS;
    const int E = in_sizes[2];
    const int nTiles = (M + 31) / 32;

    cudaFuncSetAttribute(node_gemm_persistent,
                         cudaFuncAttributeMaxDynamicSharedMemorySize, SM_TOTAL);

    prep_W<<<32, 256>>>(W1);
    node_gemm_persistent<<<296, 256, SM_TOTAL>>>(Hs, Hd, b1, M, nTiles);
    edge_score_kernel<<<(E + 15) / 16, 256>>>(src, dst, W2, b2, out, E);
}

// round 14
// speedup vs baseline: 1.3245x; 1.3245x over previous
#include <cuda_runtime.h>
#include <cuda_fp16.h>
#include <cstdint>

#define IN_FEATS 128
#define HIDDEN   256
#define NMAX     100000

// fp16 per-node projections: u = Hs@W1a + b1, v = Hd@W1b
__device__ __align__(16) unsigned short g_u[(size_t)NMAX * HIDDEN];
__device__ __align__(16) unsigned short g_v[(size_t)NMAX * HIDDEN];

// W1 fp16 swizzled B images: [isv(2)][n(256)][16 chunks of 16B]
__device__ uint4 g_Wf[2 * 256 * 16];

// ---------------------------------------------------------------------------
// helpers
// ---------------------------------------------------------------------------
__device__ __forceinline__ uint32_t smem_u32(const void* p) {
    uint32_t a;
    asm("{ .reg .u64 t; cvta.to.shared.u64 t, %1; cvt.u32.u64 %0, t; }"
        : "=r"(a) : "l"(p));
    return a;
}
__device__ __forceinline__ void cp_async16(uint32_t dst, const void* src) {
    asm volatile("cp.async.cg.shared.global [%0], [%1], 16;"
                 :: "r"(dst), "l"(src));
}
__device__ __forceinline__ void cp_async_commit() {
    asm volatile("cp.async.commit_group;");
}
__device__ __forceinline__ void cp_async_wait_all() {
    asm volatile("cp.async.wait_group 0;" ::: "memory");
}
__device__ __forceinline__ void ldsm4(uint32_t* r, uint32_t a) {
    asm volatile("ldmatrix.sync.aligned.m8n8.x4.shared.b16 {%0,%1,%2,%3}, [%4];"
                 : "=r"(r[0]), "=r"(r[1]), "=r"(r[2]), "=r"(r[3]) : "r"(a));
}
// m16n8k16 fp16 mma, fp32 accum
__device__ __forceinline__ void mma_f16(float* d, const uint32_t* a,
                                        const uint32_t* b) {
    asm volatile(
        "mma.sync.aligned.m16n8k16.row.col.f32.f16.f16.f32 "
        "{%0,%1,%2,%3}, {%4,%5,%6,%7}, {%8,%9}, {%0,%1,%2,%3};"
        : "+f"(d[0]), "+f"(d[1]), "+f"(d[2]), "+f"(d[3])
        : "r"(a[0]), "r"(a[1]), "r"(a[2]), "r"(a[3]), "r"(b[0]), "r"(b[1]));
}
__device__ __forceinline__ uint32_t pack_h2(float a, float b) {
    __half2 p = __floats2half2_rn(a, b);
    return *reinterpret_cast<uint32_t*>(&p);
}
// row-local XOR swizzle: rows 256B (128 fp16), chunk(16B) ^= (row & 7)
__device__ __forceinline__ uint32_t swz(uint32_t row, uint32_t kbyte) {
    return row * 256u + ((((kbyte >> 4) ^ (row & 7u)) << 4) | (kbyte & 15u));
}

// ---------------------------------------------------------------------------
// prep_W: W1 -> fp16 swizzled B images (one-time, 128KB, L2-resident).
// ---------------------------------------------------------------------------
__global__ __launch_bounds__(256)
void prep_W(const float* __restrict__ W1)
{
    const int idx = blockIdx.x * 256 + threadIdx.x;
    if (idx >= 2 * 256 * 16) return;
    const int isv = idx >> 12;
    const int n   = (idx >> 4) & 255;
    const int c   = idx & 15;

    uint32_t p[4];
    #pragma unroll
    for (int j = 0; j < 4; j++) {
        const float w0 = W1[(size_t)(isv * 128 + c * 8 + 2 * j) * HIDDEN + n];
        const float w1 = W1[(size_t)(isv * 128 + c * 8 + 2 * j + 1) * HIDDEN + n];
        p[j] = pack_h2(w0, w1);
    }
    const int dst = (isv * 256 + n) * 16 + (c ^ (n & 7));
    g_Wf[dst] = make_uint4(p[0], p[1], p[2], p[3]);
}

// SMEM layout (dynamic), 32-row M tiles, no staging -> 3 CTAs/SM:
static constexpr int SM_B  = 0;           // 256 rows x 256B = 64KB
static constexpr int SM_A  = 65536;       // 32 rows x 256B = 8KB
static constexpr int SM_TOTAL = 73728;

// ---------------------------------------------------------------------------
// Persistent node GEMM (fp16): 3 CTAs/SM, 32-row M tiles, B loaded once/CTA.
// Convert path: direct LDG of fp32 A into registers -> swizzled fp16 SMEM
// (no staging buffer, no cp.async wait chain). MMA/epilogue = r11-verified.
// blockIdx.x & 1 = {u, v}.
// ---------------------------------------------------------------------------
__global__ __launch_bounds__(256, 3)
void node_gemm_persistent(const float* __restrict__ Hs,
                          const float* __restrict__ Hd,
                          const float* __restrict__ b1,
                          int M, int nTiles)
{
    extern __shared__ char smem[];
    __shared__ float sB1[HIDDEN];
    const uint32_t smb = smem_u32(smem);

    const int tid  = threadIdx.x;
    const int wid  = tid >> 5;
    const int lane = tid & 31;

    const bool is_u = (blockIdx.x & 1) == 0;
    const int  cta  = blockIdx.x >> 1;
    const int  nCta = gridDim.x >> 1;
    const float* __restrict__ A = is_u ? Hs : Hd;
    unsigned short* __restrict__ C = is_u ? g_u : g_v;

    // ---- one-time: B image (64KB) + bias ----
    {
        const uint4* srcB = g_Wf + (is_u ? 0 : 4096);
        #pragma unroll
        for (int i = 0; i < 16; i++) {
            const int o = tid + i * 256;
            cp_async16(smb + SM_B + o * 16, srcB + o);
        }
        cp_async_commit();
    }
    sB1[tid] = b1[tid];
    cp_async_wait_all();
    __syncthreads();

    const int nbase = wid * 32;

    const uint32_t rowA  = (uint32_t)(lane & 15);
    const uint32_t xorA  = rowA & 7u;
    const uint32_t chA0  = (uint32_t)(lane >> 4);
    const uint32_t baseA = rowA * 256u;

    const uint32_t rowB  = (uint32_t)(nbase + (lane & 7) + ((lane >> 4) << 3));
    const uint32_t xorB  = rowB & 7u;
    const uint32_t chB0  = (uint32_t)((lane >> 3) & 1);
    const uint32_t baseB = rowB * 256u;

    // convert-thread mapping: row tid/8, k-eighth (tid&7)*16
    const int cvRow = tid >> 3;
    const int cvKq  = (tid & 7) * 16;

    for (int t = cta; t < nTiles; t += nCta) {
        const int bm = t * 32;

        // ---- load fp32 A row segment -> registers -> swizzled fp16 ----
        {
            const int grow = bm + cvRow;
            const bool valid = grow < M;
            const float* ar = A + (size_t)grow * IN_FEATS + cvKq;
            float4 x[4];
            #pragma unroll
            for (int j = 0; j < 4; j++)
                x[j] = valid ? *reinterpret_cast<const float4*>(ar + j * 4)
                             : make_float4(0.f, 0.f, 0.f, 0.f);
            #pragma unroll
            for (int j = 0; j < 4; j++) {
                const int k = cvKq + j * 4;
                uint2 hv;
                hv.x = pack_h2(x[j].x, x[j].y);
                hv.y = pack_h2(x[j].z, x[j].w);
                const uint32_t o = swz((uint32_t)cvRow, (uint32_t)(k * 2));
                *reinterpret_cast<uint2*>(smem + SM_A + o) = hv;
            }
        }
        __syncthreads();

        // ---- MMA: 8 ksteps, warp 32M x 32N ----
        float acc[2][4][4];
        #pragma unroll
        for (int mt = 0; mt < 2; mt++)
            #pragma unroll
            for (int nt = 0; nt < 4; nt++)
                #pragma unroll
                for (int q = 0; q < 4; q++) acc[mt][nt][q] = 0.f;

        #pragma unroll
        for (int ks = 0; ks < 8; ks++) {
            const uint32_t aAddr0 =
                smb + SM_A + baseA + (((chA0 + 2u * ks) ^ xorA) << 4);
            const uint32_t bAddr0 =
                smb + SM_B + baseB + (((chB0 + 2u * ks) ^ xorB) << 4);
            uint32_t af[2][4], bf[2][4];
            #pragma unroll
            for (int mt = 0; mt < 2; mt++)
                ldsm4(af[mt], aAddr0 + mt * 16 * 256);
            #pragma unroll
            for (int bt = 0; bt < 2; bt++)
                ldsm4(bf[bt], bAddr0 + bt * 16 * 256);
            #pragma unroll
            for (int mt = 0; mt < 2; mt++)
                #pragma unroll
                for (int bt = 0; bt < 2; bt++) {
                    mma_f16(acc[mt][2 * bt],     af[mt], &bf[bt][0]);
                    mma_f16(acc[mt][2 * bt + 1], af[mt], &bf[bt][2]);
                }
        }

        // ---- epilogue: +bias (u only), fp16 pack, store ----
        #pragma unroll
        for (int mt = 0; mt < 2; mt++) {
            const int m0 = mt * 16 + (lane >> 2);
            #pragma unroll
            for (int half = 0; half < 2; half++) {
                const int grow = bm + m0 + half * 8;
                if (grow >= M) continue;
                unsigned short* orow = C + (size_t)grow * HIDDEN;
                #pragma unroll
                for (int nt = 0; nt < 4; nt++) {
                    const int n = nbase + nt * 8 + (lane & 3) * 2;
                    float f0 = acc[mt][nt][2 * half];
                    float f1 = acc[mt][nt][2 * half + 1];
                    if (is_u) { f0 += sB1[n]; f1 += sB1[n + 1]; }
                    *reinterpret_cast<uint32_t*>(orow + n) = pack_h2(f0, f1);
                }
            }
        }

        __syncthreads();    // ldsm/epilogue done before next convert overwrites
    }
}

// ---------------------------------------------------------------------------
// Edge pass (r11-verified, 110us): full warp per edge, 2 edges per warp.
// ---------------------------------------------------------------------------
__global__ __launch_bounds__(256)
void edge_score_kernel(const int* __restrict__ src,
                       const int* __restrict__ dst,
                       const float* __restrict__ W2,
                       const float* __restrict__ b2,
                       float* __restrict__ out,
                       int E)
{
    __shared__ float sW2[HIDDEN];
    const int tid = threadIdx.x;
    sW2[tid] = W2[tid];
    __syncthreads();

    const int lane = tid & 31;
    const int warp = tid >> 5;

    const float4 wA = *reinterpret_cast<const float4*>(&sW2[lane * 8]);
    const float4 wB = *reinterpret_cast<const float4*>(&sW2[lane * 8 + 4]);
    const float w[8] = {wA.x, wA.y, wA.z, wA.w, wB.x, wB.y, wB.z, wB.w};
    const float bias = b2[0];

    const int e0 = (blockIdx.x * 8 + warp) * 2;
    if (e0 >= E) return;
    const bool has1 = (e0 + 1) < E;

    const int s0 = src[e0];
    const int d0 = dst[e0];
    const int s1 = has1 ? src[e0 + 1] : s0;
    const int d1 = has1 ? dst[e0 + 1] : d0;

    const uint4 u0 =
        reinterpret_cast<const uint4*>(g_u + (size_t)s0 * HIDDEN)[lane];
    const uint4 v0 =
        reinterpret_cast<const uint4*>(g_v + (size_t)d0 * HIDDEN)[lane];
    const uint4 u1 =
        reinterpret_cast<const uint4*>(g_u + (size_t)s1 * HIDDEN)[lane];
    const uint4 v1 =
        reinterpret_cast<const uint4*>(g_v + (size_t)d1 * HIDDEN)[lane];

    const __half2* u0h = reinterpret_cast<const __half2*>(&u0);
    const __half2* v0h = reinterpret_cast<const __half2*>(&v0);
    const __half2* u1h = reinterpret_cast<const __half2*>(&u1);
    const __half2* v1h = reinterpret_cast<const __half2*>(&v1);

    float acc0 = 0.f, acc1 = 0.f;
    #pragma unroll
    for (int i = 0; i < 4; i++) {
        float2 a = __half22float2(u0h[i]);
        float2 b = __half22float2(v0h[i]);
        acc0 = fmaf(fmaxf(a.x + b.x, 0.f), w[2 * i], acc0);
        acc0 = fmaf(fmaxf(a.y + b.y, 0.f), w[2 * i + 1], acc0);
        float2 c = __half22float2(u1h[i]);
        float2 d = __half22float2(v1h[i]);
        acc1 = fmaf(fmaxf(c.x + d.x, 0.f), w[2 * i], acc1);
        acc1 = fmaf(fmaxf(c.y + d.y, 0.f), w[2 * i + 1], acc1);
    }
    #pragma unroll
    for (int o = 16; o > 0; o >>= 1) {
        acc0 += __shfl_xor_sync(0xFFFFFFFFu, acc0, o);
        acc1 += __shfl_xor_sync(0xFFFFFFFFu, acc1, o);
    }

    if (lane == 0) {
        out[e0] = acc0 + bias;
        if (has1) out[e0 + 1] = acc1 + bias;
    }
}

// ---------------------------------------------------------------------------
extern "C" void kernel_launch(void* const* d_in, const int* in_sizes, int n_in,
                              void* d_out, int out_size)
{
    const float* Hs = (const float*)d_in[0];
    const float* Hd = (const float*)d_in[1];
    const int*   src = (const int*)d_in[2];
    const int*   dst = (const int*)d_in[3];
    const float* W1 = (const float*)d_in[4];
    const float* b1 = (const float*)d_in[5];
    const float* W2 = (const float*)d_in[6];
    const float* b2 = (const float*)d_in[7];
    float* out = (float*)d_out;

    const int M = in_sizes[0] / IN_FEATS;
    const int E = in_sizes[2];
    const int nTiles = (M + 31) / 32;

    cudaFuncSetAttribute(node_gemm_persistent,
                         cudaFuncAttributeMaxDynamicSharedMemorySize, SM_TOTAL);

    prep_W<<<32, 256>>>(W1);
    node_gemm_persistent<<<444, 256, SM_TOTAL>>>(Hs, Hd, b1, M, nTiles);
    edge_score_kernel<<<(E + 15) / 16, 256>>>(src, dst, W2, b2, out, E);
}

// round 15
// speedup vs baseline: 1.5199x; 1.1475x over previous
#include <cuda_runtime.h>
#include <cuda_fp16.h>
#include <cstdint>

#define IN_FEATS 128
#define HIDDEN   256
#define NMAX     100000

// fp16 per-node projections: u = Hs@W1a + b1, v = Hd@W1b
__device__ __align__(16) unsigned short g_u[(size_t)NMAX * HIDDEN];
__device__ __align__(16) unsigned short g_v[(size_t)NMAX * HIDDEN];

// ---------------------------------------------------------------------------
// helpers
// ---------------------------------------------------------------------------
__device__ __forceinline__ uint32_t smem_u32(const void* p) {
    uint32_t a;
    asm("{ .reg .u64 t; cvta.to.shared.u64 t, %1; cvt.u32.u64 %0, t; }"
        : "=r"(a) : "l"(p));
    return a;
}
__device__ __forceinline__ void cp_async16(uint32_t dst, const void* src) {
    asm volatile("cp.async.cg.shared.global [%0], [%1], 16;"
                 :: "r"(dst), "l"(src));
}
__device__ __forceinline__ void cp_async16z(uint32_t dst, const void* src,
                                            int srcsz) {
    asm volatile("cp.async.cg.shared.global [%0], [%1], 16, %2;"
                 :: "r"(dst), "l"(src), "r"(srcsz));
}
__device__ __forceinline__ void cp_async_commit() {
    asm volatile("cp.async.commit_group;");
}
__device__ __forceinline__ void cp_async_wait_all() {
    asm volatile("cp.async.wait_group 0;" ::: "memory");
}
__device__ __forceinline__ void cp_async_wait2() {
    asm volatile("cp.async.wait_group 2;" ::: "memory");
}
__device__ __forceinline__ void ldsm4(uint32_t* r, uint32_t a) {
    asm volatile("ldmatrix.sync.aligned.m8n8.x4.shared.b16 {%0,%1,%2,%3}, [%4];"
                 : "=r"(r[0]), "=r"(r[1]), "=r"(r[2]), "=r"(r[3]) : "r"(a));
}
// m16n8k16 fp16 mma, fp32 accum
__device__ __forceinline__ void mma_f16(float* d, const uint32_t* a,
                                        const uint32_t* b) {
    asm volatile(
        "mma.sync.aligned.m16n8k16.row.col.f32.f16.f16.f32 "
        "{%0,%1,%2,%3}, {%4,%5,%6,%7}, {%8,%9}, {%0,%1,%2,%3};"
        : "+f"(d[0]), "+f"(d[1]), "+f"(d[2]), "+f"(d[3])
        : "r"(a[0]), "r"(a[1]), "r"(a[2]), "r"(a[3]), "r"(b[0]), "r"(b[1]));
}
__device__ __forceinline__ uint32_t pack_h2(float a, float b) {
    __half2 p = __floats2half2_rn(a, b);
    return *reinterpret_cast<uint32_t*>(&p);
}
// row-local XOR swizzle: rows 256B (128 fp16), chunk(16B) ^= (row & 7)
__device__ __forceinline__ uint32_t swz(uint32_t row, uint32_t kbyte) {
    return row * 256u + ((((kbyte >> 4) ^ (row & 7u)) << 4) | (kbyte & 15u));
}

// SMEM layout (dynamic), r11-verified: 32-row M tiles -> 2 CTAs/SM:
static constexpr int SM_B  = 0;           // 256 rows x 256B = 64KB
static constexpr int SM_A  = 65536;       // 32 rows x 256B = 8KB
static constexpr int SM_AF = 73728;       // fp32 staging 32 x 528B = 16896
static constexpr int AF_STRIDE = 528;
static constexpr int SM_TOTAL = 90624;

// issue cp.async for fp32 A tile (32 rows x 128 f32), ZFILL beyond M
__device__ __forceinline__ void load_A_async(const float* __restrict__ A,
                                             int M, int bm, uint32_t smb,
                                             int tid)
{
    #pragma unroll
    for (int i = 0; i < 4; i++) {
        const int o   = tid + i * 256;
        const int row = o >> 5;
        const int c   = o & 31;
        const float* src = A + (size_t)(bm + row) * IN_FEATS + c * 4;
        const uint32_t dst = smb + SM_AF + row * AF_STRIDE + c * 16;
        cp_async16z(dst, src, (bm + row < M) ? 16 : 0);
    }
    cp_async_commit();
}

// ---------------------------------------------------------------------------
// Persistent node GEMM (fp16): r11 structure (2 CTAs/SM, cp.async staging,
// prefetch) with B converted IN-KERNEL from W1 (prep_W folded in).
// blockIdx.x & 1 = {u, v}.
// ---------------------------------------------------------------------------
__global__ __launch_bounds__(256, 2)
void node_gemm_persistent(const float* __restrict__ Hs,
                          const float* __restrict__ Hd,
                          const float* __restrict__ W1,
                          const float* __restrict__ b1,
                          int M, int nTiles)
{
    extern __shared__ char smem[];
    __shared__ float sB1[HIDDEN];
    const uint32_t smb = smem_u32(smem);

    const int tid  = threadIdx.x;
    const int wid  = tid >> 5;
    const int lane = tid & 31;

    const bool is_u = (blockIdx.x & 1) == 0;
    const int  cta  = blockIdx.x >> 1;
    const int  nCta = gridDim.x >> 1;
    const float* __restrict__ A = is_u ? Hs : Hd;
    unsigned short* __restrict__ C = is_u ? g_u : g_v;

    // ---- first A tile prefetch (overlaps the B convert below) ----
    if (cta < nTiles) load_A_async(A, M, cta * 32, smb, tid);

    // ---- one-time: convert W1 half -> fp16 swizzled B image in SMEM ----
    // thread = column n; B[n][k] = W1[(isv*128 + k)*HIDDEN + n];
    // reads are n-coalesced across the CTA for each k.
    {
        const float* Wcol = W1 + (is_u ? 0 : (size_t)IN_FEATS * HIDDEN) + tid;
        #pragma unroll
        for (int c = 0; c < 16; c++) {
            uint32_t p[4];
            #pragma unroll
            for (int j = 0; j < 4; j++) {
                const float w0 = Wcol[(size_t)(c * 8 + 2 * j) * HIDDEN];
                const float w1 = Wcol[(size_t)(c * 8 + 2 * j + 1) * HIDDEN];
                p[j] = pack_h2(w0, w1);
            }
            const uint32_t off =
                (uint32_t)tid * 256u + (uint32_t)(((c ^ (tid & 7)) << 4));
            *reinterpret_cast<uint4*>(smem + SM_B + off) =
                make_uint4(p[0], p[1], p[2], p[3]);
        }
    }
    sB1[tid] = b1[tid];
    cp_async_wait_all();
    __syncthreads();

    const int nbase = wid * 32;

    const uint32_t rowA  = (uint32_t)(lane & 15);
    const uint32_t xorA  = rowA & 7u;
    const uint32_t chA0  = (uint32_t)(lane >> 4);
    const uint32_t baseA = rowA * 256u;

    const uint32_t rowB  = (uint32_t)(nbase + (lane & 7) + ((lane >> 4) << 3));
    const uint32_t xorB  = rowB & 7u;
    const uint32_t chB0  = (uint32_t)((lane >> 3) & 1);
    const uint32_t baseB = rowB * 256u;

    const int cvRow = tid >> 3;
    const int cvKq  = (tid & 7) * 16;
    const char* cvStage = smem + SM_AF + cvRow * AF_STRIDE;

    for (int t = cta; t < nTiles; t += nCta) {
        const int bm = t * 32;

        // ---- convert fp32 staging -> swizzled fp16 A ----
        #pragma unroll
        for (int j = 0; j < 4; j++) {
            const int k = cvKq + j * 4;
            const float4 x = *reinterpret_cast<const float4*>(cvStage + k * 4);
            uint2 hv;
            hv.x = pack_h2(x.x, x.y);
            hv.y = pack_h2(x.z, x.w);
            const uint32_t o = swz((uint32_t)cvRow, (uint32_t)(k * 2));
            *reinterpret_cast<uint2*>(smem + SM_A + o) = hv;
        }
        __syncthreads();

        // ---- prefetch next A tile (overlaps MMA below) ----
        const int tn = t + nCta;
        if (tn < nTiles) load_A_async(A, M, tn * 32, smb, tid);

        // ---- MMA: 8 ksteps, warp 32M x 32N ----
        float acc[2][4][4];
        #pragma unroll
        for (int mt = 0; mt < 2; mt++)
            #pragma unroll
            for (int nt = 0; nt < 4; nt++)
                #pragma unroll
                for (int q = 0; q < 4; q++) acc[mt][nt][q] = 0.f;

        #pragma unroll
        for (int ks = 0; ks < 8; ks++) {
            const uint32_t aAddr0 =
                smb + SM_A + baseA + (((chA0 + 2u * ks) ^ xorA) << 4);
            const uint32_t bAddr0 =
                smb + SM_B + baseB + (((chB0 + 2u * ks) ^ xorB) << 4);
            uint32_t af[2][4], bf[2][4];
            #pragma unroll
            for (int mt = 0; mt < 2; mt++)
                ldsm4(af[mt], aAddr0 + mt * 16 * 256);
            #pragma unroll
            for (int bt = 0; bt < 2; bt++)
                ldsm4(bf[bt], bAddr0 + bt * 16 * 256);
            #pragma unroll
            for (int mt = 0; mt < 2; mt++)
                #pragma unroll
                for (int bt = 0; bt < 2; bt++) {
                    mma_f16(acc[mt][2 * bt],     af[mt], &bf[bt][0]);
                    mma_f16(acc[mt][2 * bt + 1], af[mt], &bf[bt][2]);
                }
        }

        // ---- epilogue: +bias (u only), fp16 pack, store ----
        #pragma unroll
        for (int mt = 0; mt < 2; mt++) {
            const int m0 = mt * 16 + (lane >> 2);
            #pragma unroll
            for (int half = 0; half < 2; half++) {
                const int grow = bm + m0 + half * 8;
                if (grow >= M) continue;
                unsigned short* orow = C + (size_t)grow * HIDDEN;
                #pragma unroll
                for (int nt = 0; nt < 4; nt++) {
                    const int n = nbase + nt * 8 + (lane & 3) * 2;
                    float f0 = acc[mt][nt][2 * half];
                    float f1 = acc[mt][nt][2 * half + 1];
                    if (is_u) { f0 += sB1[n]; f1 += sB1[n + 1]; }
                    *reinterpret_cast<uint32_t*>(orow + n) = pack_h2(f0, f1);
                }
            }
        }

        cp_async_wait_all();
        __syncthreads();
    }
}

// ---------------------------------------------------------------------------
// Edge pass: cp.async-pipelined gathers. 8 edges/warp, depth-4 SMEM ring.
// Lane c holds hidden dims [c*8, c*8+8) (16B chunk per table) — r11 mapping.
// Constant wait_group 2 via empty-commit padding at the tail.
// ---------------------------------------------------------------------------
#define EPW 8      // edges per warp
#define EDEPTH 4   // ring depth

__global__ __launch_bounds__(256)
void edge_score_kernel(const int* __restrict__ src,
                       const int* __restrict__ dst,
                       const float* __restrict__ W2,
                       const float* __restrict__ b2,
                       float* __restrict__ out,
                       int E)
{
    __shared__ float sW2[HIDDEN];
    __shared__ __align__(16) char sbuf[8][EDEPTH][2][512];

    const int tid = threadIdx.x;
    sW2[tid] = W2[tid];
    __syncthreads();

    const int lane = tid & 31;
    const int warp = tid >> 5;

    const float4 wA = *reinterpret_cast<const float4*>(&sW2[lane * 8]);
    const float4 wB = *reinterpret_cast<const float4*>(&sW2[lane * 8 + 4]);
    const float w[8] = {wA.x, wA.y, wA.z, wA.w, wB.x, wB.y, wB.z, wB.w};
    const float bias = b2[0];

    const int e_base = (blockIdx.x * 8 + warp) * EPW;
    if (e_base >= E) return;

    // indices for 8 edges: lanes 0-7 src, lanes 8-15 dst (clamped)
    int idx = 0;
    if (lane < 16) {
        const int e = min(e_base + (lane & 7), E - 1);
        idx = (lane < 8) ? src[e] : dst[e];
    }

    const uint32_t ubuf0 = smem_u32(&sbuf[warp][0][0][0]) + lane * 16;
    const uint32_t vbuf0 = smem_u32(&sbuf[warp][0][1][0]) + lane * 16;

    // prologue: issue stages 0..2
    #pragma unroll
    for (int st = 0; st < EDEPTH - 1; st++) {
        const int s = __shfl_sync(0xFFFFFFFFu, idx, st);
        const int d = __shfl_sync(0xFFFFFFFFu, idx, 8 + st);
        cp_async16(ubuf0 + st * 1024, g_u + (size_t)s * HIDDEN + lane * 8);
        cp_async16(vbuf0 + st * 1024, g_v + (size_t)d * HIDDEN + lane * 8);
        cp_async_commit();
    }

    #pragma unroll
    for (int i = 0; i < EPW; i++) {
        // issue stage i+3 (or an empty group to keep the count constant)
        if (i + EDEPTH - 1 < EPW) {
            const int st = i + EDEPTH - 1;
            const int s = __shfl_sync(0xFFFFFFFFu, idx, st);
            const int d = __shfl_sync(0xFFFFFFFFu, idx, 8 + st);
            const int buf = st & (EDEPTH - 1);
            cp_async16(ubuf0 + buf * 1024, g_u + (size_t)s * HIDDEN + lane * 8);
            cp_async16(vbuf0 + buf * 1024, g_v + (size_t)d * HIDDEN + lane * 8);
        }
        cp_async_commit();
        cp_async_wait2();          // stage i complete

        const int buf = i & (EDEPTH - 1);
        const uint4 ur = *reinterpret_cast<const uint4*>(
            &sbuf[warp][buf][0][lane * 16]);
        const uint4 vr = *reinterpret_cast<const uint4*>(
            &sbuf[warp][buf][1][lane * 16]);
        const __half2* uh = reinterpret_cast<const __half2*>(&ur);
        const __half2* vh = reinterpret_cast<const __half2*>(&vr);

        float acc = 0.f;
        #pragma unroll
        for (int q = 0; q < 4; q++) {
            const float2 a = __half22float2(uh[q]);
            const float2 b = __half22float2(vh[q]);
            acc = fmaf(fmaxf(a.x + b.x, 0.f), w[2 * q], acc);
            acc = fmaf(fmaxf(a.y + b.y, 0.f), w[2 * q + 1], acc);
        }
        #pragma unroll
        for (int o = 16; o > 0; o >>= 1)
            acc += __shfl_xor_sync(0xFFFFFFFFu, acc, o);

        if (lane == 0 && (e_base + i) < E)
            out[e_base + i] = acc + bias;
    }
}

// ---------------------------------------------------------------------------
extern "C" void kernel_launch(void* const* d_in, const int* in_sizes, int n_in,
                              void* d_out, int out_size)
{
    const float* Hs = (const float*)d_in[0];
    const float* Hd = (const float*)d_in[1];
    const int*   src = (const int*)d_in[2];
    const int*   dst = (const int*)d_in[3];
    const float* W1 = (const float*)d_in[4];
    const float* b1 = (const float*)d_in[5];
    const float* W2 = (const float*)d_in[6];
    const float* b2 = (const float*)d_in[7];
    float* out = (float*)d_out;

    const int M = in_sizes[0] / IN_FEATS;
    const int E = in_sizes[2];
    const int nTiles = (M + 31) / 32;

    cudaFuncSetAttribute(node_gemm_persistent,
                         cudaFuncAttributeMaxDynamicSharedMemorySize, SM_TOTAL);

    node_gemm_persistent<<<296, 256, SM_TOTAL>>>(Hs, Hd, W1, b1, M, nTiles);

    const int nWarps = (E + EPW - 1) / EPW;
    edge_score_kernel<<<(nWarps + 7) / 8, 256>>>(src, dst, W2, b2, out, E);
}

// round 16
// speedup vs baseline: 1.5948x; 1.0493x over previous
#include <cuda_runtime.h>
#include <cuda_fp16.h>
#include <cstdint>

#define IN_FEATS 128
#define HIDDEN   256
#define NMAX     100000

// fp16 per-node projections: u = Hs@W1a + b1, v = Hd@W1b
__device__ __align__(16) unsigned short g_u[(size_t)NMAX * HIDDEN];
__device__ __align__(16) unsigned short g_v[(size_t)NMAX * HIDDEN];

// ---------------------------------------------------------------------------
// helpers
// ---------------------------------------------------------------------------
__device__ __forceinline__ uint32_t smem_u32(const void* p) {
    uint32_t a;
    asm("{ .reg .u64 t; cvta.to.shared.u64 t, %1; cvt.u32.u64 %0, t; }"
        : "=r"(a) : "l"(p));
    return a;
}
__device__ __forceinline__ void cp_async16(uint32_t dst, const void* src) {
    asm volatile("cp.async.cg.shared.global [%0], [%1], 16;"
                 :: "r"(dst), "l"(src));
}
__device__ __forceinline__ void cp_async16z(uint32_t dst, const void* src,
                                            int srcsz) {
    asm volatile("cp.async.cg.shared.global [%0], [%1], 16, %2;"
                 :: "r"(dst), "l"(src), "r"(srcsz));
}
__device__ __forceinline__ void cp_async_commit() {
    asm volatile("cp.async.commit_group;");
}
__device__ __forceinline__ void cp_async_wait_all() {
    asm volatile("cp.async.wait_group 0;" ::: "memory");
}
__device__ __forceinline__ void cp_async_wait2() {
    asm volatile("cp.async.wait_group 2;" ::: "memory");
}
__device__ __forceinline__ void ldsm4(uint32_t* r, uint32_t a) {
    asm volatile("ldmatrix.sync.aligned.m8n8.x4.shared.b16 {%0,%1,%2,%3}, [%4];"
                 : "=r"(r[0]), "=r"(r[1]), "=r"(r[2]), "=r"(r[3]) : "r"(a));
}
// m16n8k16 fp16 mma, fp32 accum
__device__ __forceinline__ void mma_f16(float* d, const uint32_t* a,
                                        const uint32_t* b) {
    asm volatile(
        "mma.sync.aligned.m16n8k16.row.col.f32.f16.f16.f32 "
        "{%0,%1,%2,%3}, {%4,%5,%6,%7}, {%8,%9}, {%0,%1,%2,%3};"
        : "+f"(d[0]), "+f"(d[1]), "+f"(d[2]), "+f"(d[3])
        : "r"(a[0]), "r"(a[1]), "r"(a[2]), "r"(a[3]), "r"(b[0]), "r"(b[1]));
}
__device__ __forceinline__ uint32_t pack_h2(float a, float b) {
    __half2 p = __floats2half2_rn(a, b);
    return *reinterpret_cast<uint32_t*>(&p);
}
// row-local XOR swizzle: rows 256B (128 fp16), chunk(16B) ^= (row & 7)
__device__ __forceinline__ uint32_t swz(uint32_t row, uint32_t kbyte) {
    return row * 256u + ((((kbyte >> 4) ^ (row & 7u)) << 4) | (kbyte & 15u));
}

// SMEM layout (dynamic), r11-verified: 32-row M tiles -> 2 CTAs/SM:
static constexpr int SM_B  = 0;           // 256 rows x 256B = 64KB
static constexpr int SM_A  = 65536;       // 32 rows x 256B = 8KB
static constexpr int SM_AF = 73728;       // fp32 staging 32 x 528B = 16896
static constexpr int AF_STRIDE = 528;
static constexpr int SM_TOTAL = 90624;

// issue cp.async for fp32 A tile (32 rows x 128 f32), ZFILL beyond M
__device__ __forceinline__ void load_A_async(const float* __restrict__ A,
                                             int M, int bm, uint32_t smb,
                                             int tid)
{
    #pragma unroll
    for (int i = 0; i < 4; i++) {
        const int o   = tid + i * 256;
        const int row = o >> 5;
        const int c   = o & 31;
        const float* src = A + (size_t)(bm + row) * IN_FEATS + c * 4;
        const uint32_t dst = smb + SM_AF + row * AF_STRIDE + c * 16;
        cp_async16z(dst, src, (bm + row < M) ? 16 : 0);
    }
    cp_async_commit();
}

// ---------------------------------------------------------------------------
// Persistent node GEMM (fp16): r15-verified (prep_W folded in), unchanged.
// ---------------------------------------------------------------------------
__global__ __launch_bounds__(256, 2)
void node_gemm_persistent(const float* __restrict__ Hs,
                          const float* __restrict__ Hd,
                          const float* __restrict__ W1,
                          const float* __restrict__ b1,
                          int M, int nTiles)
{
    extern __shared__ char smem[];
    __shared__ float sB1[HIDDEN];
    const uint32_t smb = smem_u32(smem);

    const int tid  = threadIdx.x;
    const int wid  = tid >> 5;
    const int lane = tid & 31;

    const bool is_u = (blockIdx.x & 1) == 0;
    const int  cta  = blockIdx.x >> 1;
    const int  nCta = gridDim.x >> 1;
    const float* __restrict__ A = is_u ? Hs : Hd;
    unsigned short* __restrict__ C = is_u ? g_u : g_v;

    if (cta < nTiles) load_A_async(A, M, cta * 32, smb, tid);

    {
        const float* Wcol = W1 + (is_u ? 0 : (size_t)IN_FEATS * HIDDEN) + tid;
        #pragma unroll
        for (int c = 0; c < 16; c++) {
            uint32_t p[4];
            #pragma unroll
            for (int j = 0; j < 4; j++) {
                const float w0 = Wcol[(size_t)(c * 8 + 2 * j) * HIDDEN];
                const float w1 = Wcol[(size_t)(c * 8 + 2 * j + 1) * HIDDEN];
                p[j] = pack_h2(w0, w1);
            }
            const uint32_t off =
                (uint32_t)tid * 256u + (uint32_t)(((c ^ (tid & 7)) << 4));
            *reinterpret_cast<uint4*>(smem + SM_B + off) =
                make_uint4(p[0], p[1], p[2], p[3]);
        }
    }
    sB1[tid] = b1[tid];
    cp_async_wait_all();
    __syncthreads();

    const int nbase = wid * 32;

    const uint32_t rowA  = (uint32_t)(lane & 15);
    const uint32_t xorA  = rowA & 7u;
    const uint32_t chA0  = (uint32_t)(lane >> 4);
    const uint32_t baseA = rowA * 256u;

    const uint32_t rowB  = (uint32_t)(nbase + (lane & 7) + ((lane >> 4) << 3));
    const uint32_t xorB  = rowB & 7u;
    const uint32_t chB0  = (uint32_t)((lane >> 3) & 1);
    const uint32_t baseB = rowB * 256u;

    const int cvRow = tid >> 3;
    const int cvKq  = (tid & 7) * 16;
    const char* cvStage = smem + SM_AF + cvRow * AF_STRIDE;

    for (int t = cta; t < nTiles; t += nCta) {
        const int bm = t * 32;

        #pragma unroll
        for (int j = 0; j < 4; j++) {
            const int k = cvKq + j * 4;
            const float4 x = *reinterpret_cast<const float4*>(cvStage + k * 4);
            uint2 hv;
            hv.x = pack_h2(x.x, x.y);
            hv.y = pack_h2(x.z, x.w);
            const uint32_t o = swz((uint32_t)cvRow, (uint32_t)(k * 2));
            *reinterpret_cast<uint2*>(smem + SM_A + o) = hv;
        }
        __syncthreads();

        const int tn = t + nCta;
        if (tn < nTiles) load_A_async(A, M, tn * 32, smb, tid);

        float acc[2][4][4];
        #pragma unroll
        for (int mt = 0; mt < 2; mt++)
            #pragma unroll
            for (int nt = 0; nt < 4; nt++)
                #pragma unroll
                for (int q = 0; q < 4; q++) acc[mt][nt][q] = 0.f;

        #pragma unroll
        for (int ks = 0; ks < 8; ks++) {
            const uint32_t aAddr0 =
                smb + SM_A + baseA + (((chA0 + 2u * ks) ^ xorA) << 4);
            const uint32_t bAddr0 =
                smb + SM_B + baseB + (((chB0 + 2u * ks) ^ xorB) << 4);
            uint32_t af[2][4], bf[2][4];
            #pragma unroll
            for (int mt = 0; mt < 2; mt++)
                ldsm4(af[mt], aAddr0 + mt * 16 * 256);
            #pragma unroll
            for (int bt = 0; bt < 2; bt++)
                ldsm4(bf[bt], bAddr0 + bt * 16 * 256);
            #pragma unroll
            for (int mt = 0; mt < 2; mt++)
                #pragma unroll
                for (int bt = 0; bt < 2; bt++) {
                    mma_f16(acc[mt][2 * bt],     af[mt], &bf[bt][0]);
                    mma_f16(acc[mt][2 * bt + 1], af[mt], &bf[bt][2]);
                }
        }

        #pragma unroll
        for (int mt = 0; mt < 2; mt++) {
            const int m0 = mt * 16 + (lane >> 2);
            #pragma unroll
            for (int half = 0; half < 2; half++) {
                const int grow = bm + m0 + half * 8;
                if (grow >= M) continue;
                unsigned short* orow = C + (size_t)grow * HIDDEN;
                #pragma unroll
                for (int nt = 0; nt < 4; nt++) {
                    const int n = nbase + nt * 8 + (lane & 3) * 2;
                    float f0 = acc[mt][nt][2 * half];
                    float f1 = acc[mt][nt][2 * half + 1];
                    if (is_u) { f0 += sB1[n]; f1 += sB1[n + 1]; }
                    *reinterpret_cast<uint32_t*>(orow + n) = pack_h2(f0, f1);
                }
            }
        }

        cp_async_wait_all();
        __syncthreads();
    }
}

// ---------------------------------------------------------------------------
// Edge pass: cp.async ring, depth 3 (24KB -> 8 CTAs/SM), 8 edges/warp,
// fp16 SIMD add+relu (HADD2/HMAX2) — issue-count reduction.
// ---------------------------------------------------------------------------
#define EPW 8      // edges per warp
#define EDEPTH 3   // ring depth

__global__ __launch_bounds__(256)
void edge_score_kernel(const int* __restrict__ src,
                       const int* __restrict__ dst,
                       const float* __restrict__ W2,
                       const float* __restrict__ b2,
                       float* __restrict__ out,
                       int E)
{
    __shared__ float sW2[HIDDEN];
    __shared__ __align__(16) char sbuf[8][EDEPTH][2][512];

    const int tid = threadIdx.x;
    sW2[tid] = W2[tid];
    __syncthreads();

    const int lane = tid & 31;
    const int warp = tid >> 5;

    const float4 wA = *reinterpret_cast<const float4*>(&sW2[lane * 8]);
    const float4 wB = *reinterpret_cast<const float4*>(&sW2[lane * 8 + 4]);
    const float w[8] = {wA.x, wA.y, wA.z, wA.w, wB.x, wB.y, wB.z, wB.w};
    const float bias = b2[0];

    const int e_base = (blockIdx.x * 8 + warp) * EPW;
    if (e_base >= E) return;

    // indices for 8 edges: lanes 0-7 src, lanes 8-15 dst (clamped)
    int idx = 0;
    if (lane < 16) {
        const int e = min(e_base + (lane & 7), E - 1);
        idx = (lane < 8) ? src[e] : dst[e];
    }

    const uint32_t ubuf0 = smem_u32(&sbuf[warp][0][0][0]) + lane * 16;
    const uint32_t vbuf0 = smem_u32(&sbuf[warp][0][1][0]) + lane * 16;

    // prologue: issue stages 0..1
    #pragma unroll
    for (int st = 0; st < EDEPTH - 1; st++) {
        const int s = __shfl_sync(0xFFFFFFFFu, idx, st);
        const int d = __shfl_sync(0xFFFFFFFFu, idx, 8 + st);
        cp_async16(ubuf0 + st * 1024, g_u + (size_t)s * HIDDEN + lane * 8);
        cp_async16(vbuf0 + st * 1024, g_v + (size_t)d * HIDDEN + lane * 8);
        cp_async_commit();
    }

    const __half2 zero2 = __float2half2_rn(0.f);

    #pragma unroll
    for (int i = 0; i < EPW; i++) {
        // issue stage i+2 (or empty group to keep pending count semantics)
        if (i + EDEPTH - 1 < EPW) {
            const int st = i + EDEPTH - 1;
            const int s = __shfl_sync(0xFFFFFFFFu, idx, st);
            const int d = __shfl_sync(0xFFFFFFFFu, idx, 8 + st);
            const int buf = st % EDEPTH;
            cp_async16(ubuf0 + buf * 1024, g_u + (size_t)s * HIDDEN + lane * 8);
            cp_async16(vbuf0 + buf * 1024, g_v + (size_t)d * HIDDEN + lane * 8);
        }
        cp_async_commit();
        cp_async_wait2();          // stage i complete

        const int buf = i % EDEPTH;
        const uint4 ur = *reinterpret_cast<const uint4*>(
            &sbuf[warp][buf][0][lane * 16]);
        const uint4 vr = *reinterpret_cast<const uint4*>(
            &sbuf[warp][buf][1][lane * 16]);
        const __half2* uh = reinterpret_cast<const __half2*>(&ur);
        const __half2* vh = reinterpret_cast<const __half2*>(&vr);

        float acc = 0.f;
        #pragma unroll
        for (int q = 0; q < 4; q++) {
            const __half2 r = __hmax2(__hadd2(uh[q], vh[q]), zero2);
            const float2 f = __half22float2(r);
            acc = fmaf(f.x, w[2 * q], acc);
            acc = fmaf(f.y, w[2 * q + 1], acc);
        }
        #pragma unroll
        for (int o = 16; o > 0; o >>= 1)
            acc += __shfl_xor_sync(0xFFFFFFFFu, acc, o);

        if (lane == 0 && (e_base + i) < E)
            out[e_base + i] = acc + bias;
    }
}

// ---------------------------------------------------------------------------
extern "C" void kernel_launch(void* const* d_in, const int* in_sizes, int n_in,
                              void* d_out, int out_size)
{
    const float* Hs = (const float*)d_in[0];
    const float* Hd = (const float*)d_in[1];
    const int*   src = (const int*)d_in[2];
    const int*   dst = (const int*)d_in[3];
    const float* W1 = (const float*)d_in[4];
    const float* b1 = (const float*)d_in[5];
    const float* W2 = (const float*)d_in[6];
    const float* b2 = (const float*)d_in[7];
    float* out = (float*)d_out;

    const int M = in_sizes[0] / IN_FEATS;
    const int E = in_sizes[2];
    const int nTiles = (M + 31) / 32;

    cudaFuncSetAttribute(node_gemm_persistent,
                         cudaFuncAttributeMaxDynamicSharedMemorySize, SM_TOTAL);

    node_gemm_persistent<<<296, 256, SM_TOTAL>>>(Hs, Hd, W1, b1, M, nTiles);

    const int nWarps = (E + EPW - 1) / EPW;
    edge_score_kernel<<<(nWarps + 7) / 8, 256>>>(src, dst, W2, b2, out, E);
}